// round 14
// baseline (speedup 1.0000x reference)
#include <cuda_runtime.h>
#include <cstdint>
#include <cstddef>

#define MAX_N 100000
#define MAX_E 1600000

// Scratch (no cudaMalloc allowed).
__device__ float g_pre[(size_t)MAX_N * 128];   // x@W1a + b1 per node
__device__ float g_S[(size_t)MAX_N * 128];     // sum of relu(...) per node
__device__ int   g_cnt[MAX_N];                 // in-degree
__device__ int   g_off[MAX_N];                 // bucket start
__device__ int   g_cur[MAX_N];                 // bucket write cursor
__device__ int4  g_quad[MAX_E];                // {edge id, src, dst, 0} grouped by dst
__device__ int   g_cursor;                     // global bucket allocator
__device__ int   g_is64;                       // edge_index dtype flag

// ---------------------------------------------------------------------------
// Detect edge_index element width (int64 indices < 2^17 -> odd words all 0).
// ---------------------------------------------------------------------------
__global__ void detect_kernel(const int* __restrict__ ei32, int n_words) {
    __shared__ int nonzero;
    if (threadIdx.x == 0) nonzero = 0;
    __syncthreads();
    const int idx = 1 + 2 * threadIdx.x;
    if (idx < n_words && ei32[idx] != 0) atomicOr(&nonzero, 1);
    __syncthreads();
    if (threadIdx.x == 0) g_is64 = (nonzero == 0) ? 1 : 0;
}

__device__ __forceinline__ int load_idx(const void* ei_raw, int is64, size_t pos) {
    return is64 ? (int)((const long long*)ei_raw)[pos]
                : ((const int*)ei_raw)[pos];
}

// ---------------------------------------------------------------------------
// Bucket sort by destination: histogram -> offsets -> permutation.
// ---------------------------------------------------------------------------
__global__ __launch_bounds__(256) void hist_kernel(const void* __restrict__ ei_raw,
                                                   int nE, int nN) {
    const int e = blockIdx.x * blockDim.x + threadIdx.x;
    const int is64 = g_is64;
    if (e < nE) {
        const int dst = load_idx(ei_raw, is64, e);
        if ((unsigned)dst < (unsigned)nN) atomicAdd(&g_cnt[dst], 1);
    }
}

__global__ __launch_bounds__(256) void offset_kernel(int nN) {
    const int v = blockIdx.x * blockDim.x + threadIdx.x;
    const int lane = threadIdx.x & 31;
    const int c = (v < nN) ? g_cnt[v] : 0;
    int s = c;  // inclusive warp scan
#pragma unroll
    for (int d = 1; d < 32; d <<= 1) {
        const int t = __shfl_up_sync(0xffffffffu, s, d);
        if (lane >= d) s += t;
    }
    const int total = __shfl_sync(0xffffffffu, s, 31);
    int base = 0;
    if (lane == 31) base = atomicAdd(&g_cursor, total);
    base = __shfl_sync(0xffffffffu, base, 31);
    const int off = base + s - c;  // exclusive within warp
    if (v < nN) { g_off[v] = off; g_cur[v] = off; }
}

__global__ __launch_bounds__(256) void scatter_kernel(const void* __restrict__ ei_raw,
                                                      int nE, int nN) {
    const int e = blockIdx.x * blockDim.x + threadIdx.x;
    const int is64 = g_is64;
    if (e < nE) {
        const int dst = load_idx(ei_raw, is64, e);
        const int src = load_idx(ei_raw, is64, (size_t)nE + e);
        if ((unsigned)dst < (unsigned)nN && (unsigned)src < (unsigned)nN) {
            const int pos = atomicAdd(&g_cur[dst], 1);
            g_quad[pos] = make_int4(e, src, dst, 0);
        }
    }
}

// ---------------------------------------------------------------------------
// pre = x @ W1[0:128,:] + b1        (N x 128, K=128)
// ---------------------------------------------------------------------------
__global__ __launch_bounds__(256) void pre_kernel(const float* __restrict__ x,
                                                  const float* __restrict__ W1,
                                                  const float* __restrict__ b1,
                                                  int n) {
    __shared__ float As[64][33];
    __shared__ float Ws[32][128];
    const int tid = threadIdx.x;
    const int n0 = blockIdx.x * 64;
    const int rg = tid & 15;
    const int cg = tid >> 4;

    float acc[4][8];
#pragma unroll
    for (int i = 0; i < 4; i++)
#pragma unroll
        for (int j = 0; j < 8; j++) acc[i][j] = 0.f;

    for (int k0 = 0; k0 < 128; k0 += 32) {
        {
            const int r = tid >> 3;
            const int kq = (tid & 7) * 4;
#pragma unroll
            for (int rr = 0; rr < 64; rr += 32) {
                const int row = r + rr;
                const int node = n0 + row;
                float4 v = make_float4(0.f, 0.f, 0.f, 0.f);
                if (node < n) v = *(const float4*)&x[(size_t)node * 128 + k0 + kq];
                As[row][kq] = v.x; As[row][kq + 1] = v.y;
                As[row][kq + 2] = v.z; As[row][kq + 3] = v.w;
            }
        }
        {
            const int k = tid >> 5;
            const int c = (tid & 31) * 4;
#pragma unroll
            for (int kk = 0; kk < 32; kk += 8)
                *(float4*)&Ws[k + kk][c] =
                    *(const float4*)&W1[(size_t)(k0 + k + kk) * 128 + c];
        }
        __syncthreads();
#pragma unroll
        for (int k2 = 0; k2 < 32; k2++) {
            const float4 w0 = *(const float4*)&Ws[k2][cg * 8];
            const float4 w1 = *(const float4*)&Ws[k2][cg * 8 + 4];
#pragma unroll
            for (int i = 0; i < 4; i++) {
                const float a = As[rg * 4 + i][k2];
                acc[i][0] += a * w0.x; acc[i][1] += a * w0.y;
                acc[i][2] += a * w0.z; acc[i][3] += a * w0.w;
                acc[i][4] += a * w1.x; acc[i][5] += a * w1.y;
                acc[i][6] += a * w1.z; acc[i][7] += a * w1.w;
            }
        }
        __syncthreads();
    }

    const float4 bb0 = *(const float4*)&b1[cg * 8];
    const float4 bb1 = *(const float4*)&b1[cg * 8 + 4];
#pragma unroll
    for (int i = 0; i < 4; i++) {
        const int node = n0 + rg * 4 + i;
        if (node < n) {
            float4 o0 = make_float4(acc[i][0] + bb0.x, acc[i][1] + bb0.y,
                                    acc[i][2] + bb0.z, acc[i][3] + bb0.w);
            float4 o1 = make_float4(acc[i][4] + bb1.x, acc[i][5] + bb1.y,
                                    acc[i][6] + bb1.z, acc[i][7] + bb1.w);
            *(float4*)&g_pre[(size_t)node * 128 + cg * 8] = o0;
            *(float4*)&g_pre[(size_t)node * 128 + cg * 8 + 4] = o1;
        }
    }
}

// ---------------------------------------------------------------------------
// Aggregate v3: strip-parallel over sorted edges.
// Each warp owns 64 consecutive edges of g_quad (sorted by dst), pipelines
// chunk-of-4 loads across the whole strip, accumulates relu(pre[src]+ea@W1b)
// in registers, and flushes to g_S[dst] with red.v4 only on dst change
// (~N + #strips flushes total instead of E).
// ---------------------------------------------------------------------------
#define STRIP 64

struct Chunk {
    float4 pr[4];
    float  eav[4];
    int    dst[4];
    int    m;
};

__device__ __forceinline__ void load_chunk(Chunk& c, int i, int end, int lane,
                                           const float4* __restrict__ pre4,
                                           const float* __restrict__ ea) {
    c.m = end - i;
    if (c.m > 4) c.m = 4;
    int4 q = make_int4(0, 0, 0, 0);
    if (lane < c.m) q = g_quad[i + lane];
#pragma unroll
    for (int j = 0; j < 4; j++) {
        const int ej = __shfl_sync(0xffffffffu, q.x, j);
        const int sj = __shfl_sync(0xffffffffu, q.y, j);
        c.dst[j]     = __shfl_sync(0xffffffffu, q.z, j);
        if (j < c.m) {
            c.pr[j]  = pre4[(size_t)sj * 32 + lane];
            c.eav[j] = (lane < 16) ? ea[(size_t)ej * 16 + lane] : 0.f;
        }
    }
}

__device__ __forceinline__ void flush(int dst, float4& acc, int lane) {
    float* sp = &g_S[(size_t)dst * 128 + lane * 4];
    asm volatile("red.global.add.v4.f32 [%0], {%1, %2, %3, %4};"
                 :: "l"(sp), "f"(acc.x), "f"(acc.y), "f"(acc.z), "f"(acc.w)
                 : "memory");
    acc = make_float4(0.f, 0.f, 0.f, 0.f);
}

__device__ __forceinline__ void compute_chunk(const Chunk& c, float4& acc,
                                              const float4 (*W1b)[32],
                                              int lane, int next_dst) {
#pragma unroll
    for (int j = 0; j < 4; j++) {
        if (j >= c.m) break;
        float4 t = make_float4(0.f, 0.f, 0.f, 0.f);
#pragma unroll
        for (int k = 0; k < 16; k++) {
            const float a = __shfl_sync(0xffffffffu, c.eav[j], k);
            const float4 w = W1b[k][lane];
            t.x += a * w.x; t.y += a * w.y; t.z += a * w.z; t.w += a * w.w;
        }
        acc.x += fmaxf(c.pr[j].x + t.x, 0.f);
        acc.y += fmaxf(c.pr[j].y + t.y, 0.f);
        acc.z += fmaxf(c.pr[j].z + t.z, 0.f);
        acc.w += fmaxf(c.pr[j].w + t.w, 0.f);
        const int nd = (j + 1 < c.m) ? c.dst[j + 1] : next_dst;
        if (c.dst[j] != nd) flush(c.dst[j], acc, lane);  // warp-uniform
    }
}

__global__ __launch_bounds__(256) void agg_kernel(const float* __restrict__ ea,
                                                  const float* __restrict__ W1,
                                                  int nE) {
    __shared__ float4 W1b[16][32];
    const int tid = threadIdx.x;
    for (int idx = tid; idx < 512; idx += 256) {
        const int k = idx >> 5, c = idx & 31;
        W1b[k][c] = *(const float4*)&W1[(size_t)(128 + k) * 128 + c * 4];
    }
    __syncthreads();

    const int lane = tid & 31;
    const int warp = blockIdx.x * 8 + (tid >> 5);
    const int s0 = warp * STRIP;
    if (s0 >= nE) return;
    const int s1 = min(s0 + STRIP, nE);
    const float4* pre4 = (const float4*)g_pre;

    float4 acc = make_float4(0.f, 0.f, 0.f, 0.f);

    Chunk c0, c1;
    int i = s0;
    load_chunk(c0, i, s1, lane, pre4, ea);
    i += 4;
    while (i < s1) {
        load_chunk(c1, i, s1, lane, pre4, ea);     // prefetch next
        i += 4;
        compute_chunk(c0, acc, W1b, lane, c1.dst[0]);
        c0 = c1;
    }
    compute_chunk(c0, acc, W1b, lane, -1);         // forces final flush
}

// ---------------------------------------------------------------------------
// Node kernel: fused 3-GEMM chain, in-place A buffer (one 64x129 tile).
//   m  = cnt>0 ? S/cnt : 0
//   h1 = cnt>0 ? m @ W2 + b2 : 0
//   h2 = relu(h1 @ W3 + b3)
//   out = h2 @ W4 + b4
// ---------------------------------------------------------------------------
__device__ __forceinline__ void gemm128(const float* __restrict__ Ain,
                                        const float* __restrict__ Wg,
                                        float* __restrict__ Wc,
                                        float acc[4][8], int rg, int cg, int tid) {
#pragma unroll
    for (int i = 0; i < 4; i++)
#pragma unroll
        for (int j = 0; j < 8; j++) acc[i][j] = 0.f;

    for (int k0 = 0; k0 < 128; k0 += 32) {
        const int k = tid >> 5;
        const int c = (tid & 31) * 4;
#pragma unroll
        for (int kk = 0; kk < 32; kk += 8)
            *(float4*)&Wc[(k + kk) * 128 + c] =
                *(const float4*)&Wg[(size_t)(k0 + k + kk) * 128 + c];
        __syncthreads();
#pragma unroll
        for (int k2 = 0; k2 < 32; k2++) {
            const float4 w0 = *(const float4*)&Wc[k2 * 128 + cg * 8];
            const float4 w1 = *(const float4*)&Wc[k2 * 128 + cg * 8 + 4];
#pragma unroll
            for (int i = 0; i < 4; i++) {
                const float a = Ain[(rg * 4 + i) * 129 + k0 + k2];
                acc[i][0] += a * w0.x; acc[i][1] += a * w0.y;
                acc[i][2] += a * w0.z; acc[i][3] += a * w0.w;
                acc[i][4] += a * w1.x; acc[i][5] += a * w1.y;
                acc[i][6] += a * w1.z; acc[i][7] += a * w1.w;
            }
        }
        __syncthreads();   // all reads of Ain complete after this
    }
}

__global__ __launch_bounds__(256, 3) void node_kernel(const float* __restrict__ W2,
                                                      const float* __restrict__ b2,
                                                      const float* __restrict__ W3,
                                                      const float* __restrict__ b3,
                                                      const float* __restrict__ W4,
                                                      const float* __restrict__ b4,
                                                      float* __restrict__ out, int n) {
    extern __shared__ float sm[];
    float* A  = sm;                      // [64][129]
    float* Wc = sm + 64 * 129;           // [32][128]
    float* zf = Wc + 32 * 128;           // [64] cnt==0 flags

    const int tid = threadIdx.x;
    const int n0 = blockIdx.x * 64;
    const int rg = tid & 15;
    const int cg = tid >> 4;

    // Load mean operand (S/cnt) into A, flag empty nodes.
    {
        const int r = tid >> 2;
        const int q = (tid & 3) * 4;
        const int node = n0 + r;
        const int c = (node < n) ? g_cnt[node] : 0;
        const float inv = (c > 0) ? (1.f / (float)c) : 0.f;
        if ((tid & 3) == 0) zf[r] = (c > 0) ? 0.f : 1.f;
#pragma unroll
        for (int k = q; k < 128; k += 16) {
            float4 v = make_float4(0.f, 0.f, 0.f, 0.f);
            if (node < n) v = *(const float4*)&g_S[(size_t)node * 128 + k];
            A[r * 129 + k]     = v.x * inv;
            A[r * 129 + k + 1] = v.y * inv;
            A[r * 129 + k + 2] = v.z * inv;
            A[r * 129 + k + 3] = v.w * inv;
        }
    }
    __syncthreads();

    float acc[4][8];

    // Stage 1: A = (cnt>0) ? A@W2 + b2 : 0    (in place — reads done pre-sync)
    gemm128(A, W2, Wc, acc, rg, cg, tid);
    {
        const float4 bb0 = *(const float4*)&b2[cg * 8];
        const float4 bb1 = *(const float4*)&b2[cg * 8 + 4];
        const float bb[8] = {bb0.x, bb0.y, bb0.z, bb0.w, bb1.x, bb1.y, bb1.z, bb1.w};
#pragma unroll
        for (int i = 0; i < 4; i++) {
            const int row = rg * 4 + i;
            const float zero = zf[row];
#pragma unroll
            for (int j = 0; j < 8; j++)
                A[row * 129 + cg * 8 + j] = (zero > 0.f) ? 0.f : (acc[i][j] + bb[j]);
        }
    }
    __syncthreads();

    // Stage 2: A = relu(A@W3 + b3)
    gemm128(A, W3, Wc, acc, rg, cg, tid);
    {
        const float4 bb0 = *(const float4*)&b3[cg * 8];
        const float4 bb1 = *(const float4*)&b3[cg * 8 + 4];
        const float bb[8] = {bb0.x, bb0.y, bb0.z, bb0.w, bb1.x, bb1.y, bb1.z, bb1.w};
#pragma unroll
        for (int i = 0; i < 4; i++) {
            const int row = rg * 4 + i;
#pragma unroll
            for (int j = 0; j < 8; j++)
                A[row * 129 + cg * 8 + j] = fmaxf(acc[i][j] + bb[j], 0.f);
        }
    }
    __syncthreads();

    // Stage 3: out = A@W4 + b4
    gemm128(A, W4, Wc, acc, rg, cg, tid);
    {
        const float4 bb0 = *(const float4*)&b4[cg * 8];
        const float4 bb1 = *(const float4*)&b4[cg * 8 + 4];
#pragma unroll
        for (int i = 0; i < 4; i++) {
            const int node = n0 + rg * 4 + i;
            if (node < n) {
                float4 o0 = make_float4(acc[i][0] + bb0.x, acc[i][1] + bb0.y,
                                        acc[i][2] + bb0.z, acc[i][3] + bb0.w);
                float4 o1 = make_float4(acc[i][4] + bb1.x, acc[i][5] + bb1.y,
                                        acc[i][6] + bb1.z, acc[i][7] + bb1.w);
                *(float4*)&out[(size_t)node * 128 + cg * 8] = o0;
                *(float4*)&out[(size_t)node * 128 + cg * 8 + 4] = o1;
            }
        }
    }
}

// ---------------------------------------------------------------------------
extern "C" void kernel_launch(void* const* d_in, const int* in_sizes, int n_in,
                              void* d_out, int out_size) {
    const float* x  = (const float*)d_in[0];
    const void*  ei = d_in[1];          // int32 or int64 — detected on device
    const float* ea = (const float*)d_in[2];
    // d_in[3] = batch (unused)
    const float* W1 = (const float*)d_in[4];
    const float* b1 = (const float*)d_in[5];
    const float* W2 = (const float*)d_in[6];
    const float* b2 = (const float*)d_in[7];
    const float* W3 = (const float*)d_in[8];
    const float* b3 = (const float*)d_in[9];
    const float* W4 = (const float*)d_in[10];
    const float* b4 = (const float*)d_in[11];
    float* out = (float*)d_out;

    const int n  = in_sizes[0] / 128;   // nodes
    const int nE = in_sizes[1] / 2;     // edges

    void* pC = nullptr; void* pX = nullptr; void* pS = nullptr;
    cudaGetSymbolAddress(&pC, g_cnt);
    cudaGetSymbolAddress(&pX, g_cursor);
    cudaGetSymbolAddress(&pS, g_S);
    cudaMemsetAsync(pC, 0, (size_t)n * sizeof(int), 0);
    cudaMemsetAsync(pX, 0, sizeof(int), 0);
    cudaMemsetAsync(pS, 0, (size_t)n * 128 * sizeof(float), 0);

    const int ebl = (nE + 255) / 256;
    const int nbl = (n + 255) / 256;

    detect_kernel<<<1, 256>>>((const int*)ei, 2 * nE);
    hist_kernel<<<ebl, 256>>>(ei, nE, n);
    offset_kernel<<<nbl, 256>>>(n);
    scatter_kernel<<<ebl, 256>>>(ei, nE, n);

    const int nb64 = (n + 63) / 64;
    pre_kernel<<<nb64, 256>>>(x, W1, b1, n);

    const int nwarps = (nE + STRIP - 1) / STRIP;
    agg_kernel<<<(nwarps + 7) / 8, 256>>>(ea, W1, nE);

    const size_t shmem = (size_t)(64 * 129 + 32 * 128 + 64) * sizeof(float);
    cudaFuncSetAttribute(node_kernel,
                         cudaFuncAttributeMaxDynamicSharedMemorySize, (int)shmem);
    node_kernel<<<nb64, 256, shmem>>>(W2, b2, W3, b3, W4, b4, out, n);
}

// round 15
// speedup vs baseline: 1.1826x; 1.1826x over previous
#include <cuda_runtime.h>
#include <cstdint>
#include <cstddef>

#define MAX_N 100000
#define MAX_E 1600000

// Scratch (no cudaMalloc allowed).
__device__ float g_pre[(size_t)MAX_N * 128];   // x@W1a + b1 per node
__device__ float g_M[(size_t)MAX_N * 128];     // mean of relu(...) per node
__device__ int   g_cnt[MAX_N];                 // in-degree
__device__ int   g_off[MAX_N];                 // bucket start
__device__ int   g_cur[MAX_N];                 // bucket write cursor
__device__ int2  g_pairs[MAX_E];               // {edge id, src node} grouped by dst
__device__ int   g_cursor;                     // global bucket allocator
__device__ int   g_is64;                       // edge_index dtype flag

// ---------------------------------------------------------------------------
// Detect edge_index element width (int64 indices < 2^17 -> odd words all 0).
// ---------------------------------------------------------------------------
__global__ void detect_kernel(const int* __restrict__ ei32, int n_words) {
    __shared__ int nonzero;
    if (threadIdx.x == 0) nonzero = 0;
    __syncthreads();
    const int idx = 1 + 2 * threadIdx.x;
    if (idx < n_words && ei32[idx] != 0) atomicOr(&nonzero, 1);
    __syncthreads();
    if (threadIdx.x == 0) g_is64 = (nonzero == 0) ? 1 : 0;
}

__device__ __forceinline__ int load_idx(const void* ei_raw, int is64, size_t pos) {
    return is64 ? (int)((const long long*)ei_raw)[pos]
                : ((const int*)ei_raw)[pos];
}

// ---------------------------------------------------------------------------
// Bucket sort by destination: histogram -> offsets -> permutation.
// ---------------------------------------------------------------------------
__global__ __launch_bounds__(256) void hist_kernel(const void* __restrict__ ei_raw,
                                                   int nE, int nN) {
    const int e = blockIdx.x * blockDim.x + threadIdx.x;
    const int is64 = g_is64;
    if (e < nE) {
        const int dst = load_idx(ei_raw, is64, e);
        if ((unsigned)dst < (unsigned)nN) atomicAdd(&g_cnt[dst], 1);
    }
}

__global__ __launch_bounds__(256) void offset_kernel(int nN) {
    const int v = blockIdx.x * blockDim.x + threadIdx.x;
    const int lane = threadIdx.x & 31;
    const int c = (v < nN) ? g_cnt[v] : 0;
    int s = c;  // inclusive warp scan
#pragma unroll
    for (int d = 1; d < 32; d <<= 1) {
        const int t = __shfl_up_sync(0xffffffffu, s, d);
        if (lane >= d) s += t;
    }
    const int total = __shfl_sync(0xffffffffu, s, 31);
    int base = 0;
    if (lane == 31) base = atomicAdd(&g_cursor, total);
    base = __shfl_sync(0xffffffffu, base, 31);
    const int off = base + s - c;  // exclusive within warp
    if (v < nN) { g_off[v] = off; g_cur[v] = off; }
}

__global__ __launch_bounds__(256) void scatter_kernel(const void* __restrict__ ei_raw,
                                                      int nE, int nN) {
    const int e = blockIdx.x * blockDim.x + threadIdx.x;
    const int is64 = g_is64;
    if (e < nE) {
        const int dst = load_idx(ei_raw, is64, e);
        const int src = load_idx(ei_raw, is64, (size_t)nE + e);
        if ((unsigned)dst < (unsigned)nN && (unsigned)src < (unsigned)nN) {
            const int pos = atomicAdd(&g_cur[dst], 1);
            g_pairs[pos] = make_int2(e, src);
        }
    }
}

// ---------------------------------------------------------------------------
// pre = x @ W1[0:128,:] + b1        (N x 128, K=128)
// ---------------------------------------------------------------------------
__global__ __launch_bounds__(256) void pre_kernel(const float* __restrict__ x,
                                                  const float* __restrict__ W1,
                                                  const float* __restrict__ b1,
                                                  int n) {
    __shared__ float As[64][33];
    __shared__ float Ws[32][128];
    const int tid = threadIdx.x;
    const int n0 = blockIdx.x * 64;
    const int rg = tid & 15;
    const int cg = tid >> 4;

    float acc[4][8];
#pragma unroll
    for (int i = 0; i < 4; i++)
#pragma unroll
        for (int j = 0; j < 8; j++) acc[i][j] = 0.f;

    for (int k0 = 0; k0 < 128; k0 += 32) {
        {
            const int r = tid >> 3;
            const int kq = (tid & 7) * 4;
#pragma unroll
            for (int rr = 0; rr < 64; rr += 32) {
                const int row = r + rr;
                const int node = n0 + row;
                float4 v = make_float4(0.f, 0.f, 0.f, 0.f);
                if (node < n) v = *(const float4*)&x[(size_t)node * 128 + k0 + kq];
                As[row][kq] = v.x; As[row][kq + 1] = v.y;
                As[row][kq + 2] = v.z; As[row][kq + 3] = v.w;
            }
        }
        {
            const int k = tid >> 5;
            const int c = (tid & 31) * 4;
#pragma unroll
            for (int kk = 0; kk < 32; kk += 8)
                *(float4*)&Ws[k + kk][c] =
                    *(const float4*)&W1[(size_t)(k0 + k + kk) * 128 + c];
        }
        __syncthreads();
#pragma unroll
        for (int k2 = 0; k2 < 32; k2++) {
            const float4 w0 = *(const float4*)&Ws[k2][cg * 8];
            const float4 w1 = *(const float4*)&Ws[k2][cg * 8 + 4];
#pragma unroll
            for (int i = 0; i < 4; i++) {
                const float a = As[rg * 4 + i][k2];
                acc[i][0] += a * w0.x; acc[i][1] += a * w0.y;
                acc[i][2] += a * w0.z; acc[i][3] += a * w0.w;
                acc[i][4] += a * w1.x; acc[i][5] += a * w1.y;
                acc[i][6] += a * w1.z; acc[i][7] += a * w1.w;
            }
        }
        __syncthreads();
    }

    const float4 bb0 = *(const float4*)&b1[cg * 8];
    const float4 bb1 = *(const float4*)&b1[cg * 8 + 4];
#pragma unroll
    for (int i = 0; i < 4; i++) {
        const int node = n0 + rg * 4 + i;
        if (node < n) {
            float4 o0 = make_float4(acc[i][0] + bb0.x, acc[i][1] + bb0.y,
                                    acc[i][2] + bb0.z, acc[i][3] + bb0.w);
            float4 o1 = make_float4(acc[i][4] + bb1.x, acc[i][5] + bb1.y,
                                    acc[i][6] + bb1.z, acc[i][7] + bb1.w);
            *(float4*)&g_pre[(size_t)node * 128 + cg * 8] = o0;
            *(float4*)&g_pre[(size_t)node * 128 + cg * 8 + 4] = o1;
        }
    }
}

// ---------------------------------------------------------------------------
// Aggregate (R12 version): one warp per node, chunk-of-4 software pipeline.
//   M[v] = mean_e relu(pre[src_e] + ea[e] @ W1[128:144,:])
// No atomics: each warp owns its node's bucket and writes the mean directly.
// ---------------------------------------------------------------------------
struct Chunk {
    float4 pr[4];
    float  eav[4];
    int    m;
};

__device__ __forceinline__ void load_chunk(Chunk& c, int i, int end, int lane,
                                           const float4* __restrict__ pre4,
                                           const float* __restrict__ ea) {
    c.m = end - i;
    if (c.m > 4) c.m = 4;
    int2 p = make_int2(0, 0);
    if (lane < c.m) p = g_pairs[i + lane];
#pragma unroll
    for (int j = 0; j < 4; j++) {
        const int ej = __shfl_sync(0xffffffffu, p.x, j);
        const int sj = __shfl_sync(0xffffffffu, p.y, j);
        if (j < c.m) {
            c.pr[j]  = pre4[(size_t)sj * 32 + lane];
            c.eav[j] = (lane < 16) ? ea[(size_t)ej * 16 + lane] : 0.f;
        }
    }
}

__device__ __forceinline__ void compute_chunk(const Chunk& c, float4& acc,
                                              const float4 (*W1b)[32], int lane) {
#pragma unroll
    for (int j = 0; j < 4; j++) {
        if (j >= c.m) break;
        float4 t = make_float4(0.f, 0.f, 0.f, 0.f);
#pragma unroll
        for (int k = 0; k < 16; k++) {
            const float a = __shfl_sync(0xffffffffu, c.eav[j], k);
            const float4 w = W1b[k][lane];
            t.x += a * w.x; t.y += a * w.y; t.z += a * w.z; t.w += a * w.w;
        }
        acc.x += fmaxf(c.pr[j].x + t.x, 0.f);
        acc.y += fmaxf(c.pr[j].y + t.y, 0.f);
        acc.z += fmaxf(c.pr[j].z + t.z, 0.f);
        acc.w += fmaxf(c.pr[j].w + t.w, 0.f);
    }
}

__global__ __launch_bounds__(256) void agg_kernel(const float* __restrict__ ea,
                                                  const float* __restrict__ W1,
                                                  int nN) {
    __shared__ float4 W1b[16][32];
    const int tid = threadIdx.x;
    for (int idx = tid; idx < 512; idx += 256) {
        const int k = idx >> 5, c = idx & 31;
        W1b[k][c] = *(const float4*)&W1[(size_t)(128 + k) * 128 + c * 4];
    }
    __syncthreads();

    const int lane = tid & 31;
    const int v = blockIdx.x * 8 + (tid >> 5);
    if (v >= nN) return;

    const int beg = g_off[v];
    const int cnt = g_cnt[v];
    const int end = beg + cnt;
    const float4* pre4 = (const float4*)g_pre;

    float4 acc = make_float4(0.f, 0.f, 0.f, 0.f);

    Chunk c0, c1;
    int i = beg;
    if (i < end) {
        load_chunk(c0, i, end, lane, pre4, ea);
        i += 4;
        while (i < end) {
            load_chunk(c1, i, end, lane, pre4, ea);   // prefetch next
            i += 4;
            compute_chunk(c0, acc, W1b, lane);        // compute current
            c0 = c1;
        }
        compute_chunk(c0, acc, W1b, lane);
    }

    const float inv = (cnt > 0) ? (1.f / (float)cnt) : 0.f;
    acc.x *= inv; acc.y *= inv; acc.z *= inv; acc.w *= inv;
    ((float4*)g_M)[(size_t)v * 32 + lane] = acc;
}

// ---------------------------------------------------------------------------
// Node kernel: fused 3-GEMM chain, in-place single A buffer (3 blocks/SM).
//   h1 = cnt>0 ? M @ W2 + b2 : 0
//   h2 = relu(h1 @ W3 + b3)
//   out = h2 @ W4 + b4
// ---------------------------------------------------------------------------
__device__ __forceinline__ void gemm128(const float* __restrict__ Ain,
                                        const float* __restrict__ Wg,
                                        float* __restrict__ Wc,
                                        float acc[4][8], int rg, int cg, int tid) {
#pragma unroll
    for (int i = 0; i < 4; i++)
#pragma unroll
        for (int j = 0; j < 8; j++) acc[i][j] = 0.f;

    for (int k0 = 0; k0 < 128; k0 += 32) {
        const int k = tid >> 5;
        const int c = (tid & 31) * 4;
#pragma unroll
        for (int kk = 0; kk < 32; kk += 8)
            *(float4*)&Wc[(k + kk) * 128 + c] =
                *(const float4*)&Wg[(size_t)(k0 + k + kk) * 128 + c];
        __syncthreads();
#pragma unroll
        for (int k2 = 0; k2 < 32; k2++) {
            const float4 w0 = *(const float4*)&Wc[k2 * 128 + cg * 8];
            const float4 w1 = *(const float4*)&Wc[k2 * 128 + cg * 8 + 4];
#pragma unroll
            for (int i = 0; i < 4; i++) {
                const float a = Ain[(rg * 4 + i) * 129 + k0 + k2];
                acc[i][0] += a * w0.x; acc[i][1] += a * w0.y;
                acc[i][2] += a * w0.z; acc[i][3] += a * w0.w;
                acc[i][4] += a * w1.x; acc[i][5] += a * w1.y;
                acc[i][6] += a * w1.z; acc[i][7] += a * w1.w;
            }
        }
        __syncthreads();   // all reads of Ain complete after this
    }
}

__global__ __launch_bounds__(256, 3) void node_kernel(const float* __restrict__ W2,
                                                      const float* __restrict__ b2,
                                                      const float* __restrict__ W3,
                                                      const float* __restrict__ b3,
                                                      const float* __restrict__ W4,
                                                      const float* __restrict__ b4,
                                                      float* __restrict__ out, int n) {
    extern __shared__ float sm[];
    float* A  = sm;                      // [64][129]
    float* Wc = sm + 64 * 129;           // [32][128]
    float* zf = Wc + 32 * 128;           // [64] cnt==0 flags

    const int tid = threadIdx.x;
    const int n0 = blockIdx.x * 64;
    const int rg = tid & 15;
    const int cg = tid >> 4;

    // Load mean operand (already divided) into A, flag empty nodes.
    {
        const int r = tid >> 2;
        const int q = (tid & 3) * 4;
        const int node = n0 + r;
        if ((tid & 3) == 0)
            zf[r] = (node < n && g_cnt[node] > 0) ? 0.f : 1.f;
#pragma unroll
        for (int k = q; k < 128; k += 16) {
            float4 v = make_float4(0.f, 0.f, 0.f, 0.f);
            if (node < n) v = *(const float4*)&g_M[(size_t)node * 128 + k];
            A[r * 129 + k]     = v.x;
            A[r * 129 + k + 1] = v.y;
            A[r * 129 + k + 2] = v.z;
            A[r * 129 + k + 3] = v.w;
        }
    }
    __syncthreads();

    float acc[4][8];

    // Stage 1: A = (cnt>0) ? A@W2 + b2 : 0   (in place — reads done pre-sync)
    gemm128(A, W2, Wc, acc, rg, cg, tid);
    {
        const float4 bb0 = *(const float4*)&b2[cg * 8];
        const float4 bb1 = *(const float4*)&b2[cg * 8 + 4];
        const float bb[8] = {bb0.x, bb0.y, bb0.z, bb0.w, bb1.x, bb1.y, bb1.z, bb1.w};
#pragma unroll
        for (int i = 0; i < 4; i++) {
            const int row = rg * 4 + i;
            const float zero = zf[row];
#pragma unroll
            for (int j = 0; j < 8; j++)
                A[row * 129 + cg * 8 + j] = (zero > 0.f) ? 0.f : (acc[i][j] + bb[j]);
        }
    }
    __syncthreads();

    // Stage 2: A = relu(A@W3 + b3)
    gemm128(A, W3, Wc, acc, rg, cg, tid);
    {
        const float4 bb0 = *(const float4*)&b3[cg * 8];
        const float4 bb1 = *(const float4*)&b3[cg * 8 + 4];
        const float bb[8] = {bb0.x, bb0.y, bb0.z, bb0.w, bb1.x, bb1.y, bb1.z, bb1.w};
#pragma unroll
        for (int i = 0; i < 4; i++) {
            const int row = rg * 4 + i;
#pragma unroll
            for (int j = 0; j < 8; j++)
                A[row * 129 + cg * 8 + j] = fmaxf(acc[i][j] + bb[j], 0.f);
        }
    }
    __syncthreads();

    // Stage 3: out = A@W4 + b4
    gemm128(A, W4, Wc, acc, rg, cg, tid);
    {
        const float4 bb0 = *(const float4*)&b4[cg * 8];
        const float4 bb1 = *(const float4*)&b4[cg * 8 + 4];
#pragma unroll
        for (int i = 0; i < 4; i++) {
            const int node = n0 + rg * 4 + i;
            if (node < n) {
                float4 o0 = make_float4(acc[i][0] + bb0.x, acc[i][1] + bb0.y,
                                        acc[i][2] + bb0.z, acc[i][3] + bb0.w);
                float4 o1 = make_float4(acc[i][4] + bb1.x, acc[i][5] + bb1.y,
                                        acc[i][6] + bb1.z, acc[i][7] + bb1.w);
                *(float4*)&out[(size_t)node * 128 + cg * 8] = o0;
                *(float4*)&out[(size_t)node * 128 + cg * 8 + 4] = o1;
            }
        }
    }
}

// ---------------------------------------------------------------------------
extern "C" void kernel_launch(void* const* d_in, const int* in_sizes, int n_in,
                              void* d_out, int out_size) {
    const float* x  = (const float*)d_in[0];
    const void*  ei = d_in[1];          // int32 or int64 — detected on device
    const float* ea = (const float*)d_in[2];
    // d_in[3] = batch (unused)
    const float* W1 = (const float*)d_in[4];
    const float* b1 = (const float*)d_in[5];
    const float* W2 = (const float*)d_in[6];
    const float* b2 = (const float*)d_in[7];
    const float* W3 = (const float*)d_in[8];
    const float* b3 = (const float*)d_in[9];
    const float* W4 = (const float*)d_in[10];
    const float* b4 = (const float*)d_in[11];
    float* out = (float*)d_out;

    const int n  = in_sizes[0] / 128;   // nodes
    const int nE = in_sizes[1] / 2;     // edges

    // One-time side stream + events for capture-legal fork/join (no device
    // memory involved; handles are reused deterministically every call).
    static cudaStream_t s2 = nullptr;
    static cudaEvent_t evFork = nullptr, evJoin = nullptr;
    if (s2 == nullptr) {
        cudaStreamCreateWithFlags(&s2, cudaStreamNonBlocking);
        cudaEventCreateWithFlags(&evFork, cudaEventDisableTiming);
        cudaEventCreateWithFlags(&evJoin, cudaEventDisableTiming);
    }

    void* pC = nullptr; void* pX = nullptr;
    cudaGetSymbolAddress(&pC, g_cnt);
    cudaGetSymbolAddress(&pX, g_cursor);

    // Fork: pre_kernel (independent of the sort phase) runs on s2.
    cudaEventRecord(evFork, 0);
    cudaStreamWaitEvent(s2, evFork, 0);
    const int nb64 = (n + 63) / 64;
    pre_kernel<<<nb64, 256, 0, s2>>>(x, W1, b1, n);
    cudaEventRecord(evJoin, s2);

    // Sort phase on the main stream.
    cudaMemsetAsync(pC, 0, (size_t)n * sizeof(int), 0);
    cudaMemsetAsync(pX, 0, sizeof(int), 0);

    const int ebl = (nE + 255) / 256;
    const int nbl = (n + 255) / 256;
    detect_kernel<<<1, 256>>>((const int*)ei, 2 * nE);
    hist_kernel<<<ebl, 256>>>(ei, nE, n);
    offset_kernel<<<nbl, 256>>>(n);
    scatter_kernel<<<ebl, 256>>>(ei, nE, n);

    // Join: agg needs both the sorted pairs and g_pre.
    cudaStreamWaitEvent(0, evJoin, 0);
    agg_kernel<<<(n + 7) / 8, 256>>>(ea, W1, n);

    const size_t shmem = (size_t)(64 * 129 + 32 * 128 + 64) * sizeof(float);
    cudaFuncSetAttribute(node_kernel,
                         cudaFuncAttributeMaxDynamicSharedMemorySize, (int)shmem);
    node_kernel<<<nb64, 256, shmem>>>(W2, b2, W3, b3, W4, b4, out, n);
}

// round 17
// speedup vs baseline: 1.1919x; 1.0079x over previous
#include <cuda_runtime.h>
#include <cstdint>
#include <cstddef>

#define MAX_N 100000
#define MAX_E 1600000

// Blackwell packed-f32 helpers (only reachable via PTX; ptxas won't auto-fuse).
#define FMA_F32X2(d, a, b, c) \
    asm("fma.rn.f32x2 %0, %1, %2, %3;" : "=l"(d) : "l"(a), "l"(b), "l"(c))
#define PACK_F32X2(out, lo, hi) \
    asm("mov.b64 %0, {%1, %2};" : "=l"(out) : "f"(lo), "f"(hi))
#define UNPACK_F32X2(lo, hi, in) \
    asm("mov.b64 {%0, %1}, %2;" : "=f"(lo), "=f"(hi) : "l"(in))

// Scratch (no cudaMalloc allowed).
__device__ float g_pre[(size_t)MAX_N * 128];   // x@W1a + b1 per node
__device__ float g_M[(size_t)MAX_N * 128];     // mean of relu(...) per node
__device__ int   g_cnt[MAX_N];                 // in-degree
__device__ int   g_off[MAX_N];                 // bucket start
__device__ int   g_cur[MAX_N];                 // bucket write cursor
__device__ int2  g_pairs[MAX_E];               // {edge id, src node} grouped by dst
__device__ int   g_cursor;                     // global bucket allocator
__device__ int   g_is64;                       // edge_index dtype flag

// ---------------------------------------------------------------------------
// Detect edge_index element width (int64 indices < 2^17 -> odd words all 0).
// ---------------------------------------------------------------------------
__global__ void detect_kernel(const int* __restrict__ ei32, int n_words) {
    __shared__ int nonzero;
    if (threadIdx.x == 0) nonzero = 0;
    __syncthreads();
    const int idx = 1 + 2 * threadIdx.x;
    if (idx < n_words && ei32[idx] != 0) atomicOr(&nonzero, 1);
    __syncthreads();
    if (threadIdx.x == 0) g_is64 = (nonzero == 0) ? 1 : 0;
}

__device__ __forceinline__ int load_idx(const void* ei_raw, int is64, size_t pos) {
    return is64 ? (int)((const long long*)ei_raw)[pos]
                : ((const int*)ei_raw)[pos];
}

// ---------------------------------------------------------------------------
// Bucket sort by destination: histogram -> offsets -> permutation.
// ---------------------------------------------------------------------------
__global__ __launch_bounds__(256) void hist_kernel(const void* __restrict__ ei_raw,
                                                   int nE, int nN) {
    const int e = blockIdx.x * blockDim.x + threadIdx.x;
    const int is64 = g_is64;
    if (e < nE) {
        const int dst = load_idx(ei_raw, is64, e);
        if ((unsigned)dst < (unsigned)nN) atomicAdd(&g_cnt[dst], 1);
    }
}

__global__ __launch_bounds__(256) void offset_kernel(int nN) {
    const int v = blockIdx.x * blockDim.x + threadIdx.x;
    const int lane = threadIdx.x & 31;
    const int c = (v < nN) ? g_cnt[v] : 0;
    int s = c;  // inclusive warp scan
#pragma unroll
    for (int d = 1; d < 32; d <<= 1) {
        const int t = __shfl_up_sync(0xffffffffu, s, d);
        if (lane >= d) s += t;
    }
    const int total = __shfl_sync(0xffffffffu, s, 31);
    int base = 0;
    if (lane == 31) base = atomicAdd(&g_cursor, total);
    base = __shfl_sync(0xffffffffu, base, 31);
    const int off = base + s - c;  // exclusive within warp
    if (v < nN) { g_off[v] = off; g_cur[v] = off; }
}

__global__ __launch_bounds__(256) void scatter_kernel(const void* __restrict__ ei_raw,
                                                      int nE, int nN) {
    const int e = blockIdx.x * blockDim.x + threadIdx.x;
    const int is64 = g_is64;
    if (e < nE) {
        const int dst = load_idx(ei_raw, is64, e);
        const int src = load_idx(ei_raw, is64, (size_t)nE + e);
        if ((unsigned)dst < (unsigned)nN && (unsigned)src < (unsigned)nN) {
            const int pos = atomicAdd(&g_cur[dst], 1);
            g_pairs[pos] = make_int2(e, src);
        }
    }
}

// ---------------------------------------------------------------------------
// pre = x @ W1[0:128,:] + b1        (N x 128, K=128), f32x2 inner loop
// ---------------------------------------------------------------------------
__global__ __launch_bounds__(256) void pre_kernel(const float* __restrict__ x,
                                                  const float* __restrict__ W1,
                                                  const float* __restrict__ b1,
                                                  int n) {
    __shared__ float As[64][33];
    __shared__ __align__(16) float Ws[32][128];
    const int tid = threadIdx.x;
    const int n0 = blockIdx.x * 64;
    const int rg = tid & 15;
    const int cg = tid >> 4;

    unsigned long long acc2[4][4];
#pragma unroll
    for (int i = 0; i < 4; i++)
#pragma unroll
        for (int j = 0; j < 4; j++) acc2[i][j] = 0ull;

    for (int k0 = 0; k0 < 128; k0 += 32) {
        {
            const int r = tid >> 3;
            const int kq = (tid & 7) * 4;
#pragma unroll
            for (int rr = 0; rr < 64; rr += 32) {
                const int row = r + rr;
                const int node = n0 + row;
                float4 v = make_float4(0.f, 0.f, 0.f, 0.f);
                if (node < n) v = *(const float4*)&x[(size_t)node * 128 + k0 + kq];
                As[row][kq] = v.x; As[row][kq + 1] = v.y;
                As[row][kq + 2] = v.z; As[row][kq + 3] = v.w;
            }
        }
        {
            const int k = tid >> 5;
            const int c = (tid & 31) * 4;
#pragma unroll
            for (int kk = 0; kk < 32; kk += 8)
                *(float4*)&Ws[k + kk][c] =
                    *(const float4*)&W1[(size_t)(k0 + k + kk) * 128 + c];
        }
        __syncthreads();
#pragma unroll
        for (int k2 = 0; k2 < 32; k2++) {
            const ulonglong2 wa = *(const ulonglong2*)&Ws[k2][cg * 8];
            const ulonglong2 wb = *(const ulonglong2*)&Ws[k2][cg * 8 + 4];
#pragma unroll
            for (int i = 0; i < 4; i++) {
                const float a = As[rg * 4 + i][k2];
                unsigned long long ap; PACK_F32X2(ap, a, a);
                FMA_F32X2(acc2[i][0], ap, wa.x, acc2[i][0]);
                FMA_F32X2(acc2[i][1], ap, wa.y, acc2[i][1]);
                FMA_F32X2(acc2[i][2], ap, wb.x, acc2[i][2]);
                FMA_F32X2(acc2[i][3], ap, wb.y, acc2[i][3]);
            }
        }
        __syncthreads();
    }

    const float4 bb0 = *(const float4*)&b1[cg * 8];
    const float4 bb1 = *(const float4*)&b1[cg * 8 + 4];
#pragma unroll
    for (int i = 0; i < 4; i++) {
        const int node = n0 + rg * 4 + i;
        if (node < n) {
            float a0, a1, a2, a3, a4, a5, a6, a7;
            UNPACK_F32X2(a0, a1, acc2[i][0]);
            UNPACK_F32X2(a2, a3, acc2[i][1]);
            UNPACK_F32X2(a4, a5, acc2[i][2]);
            UNPACK_F32X2(a6, a7, acc2[i][3]);
            float4 o0 = make_float4(a0 + bb0.x, a1 + bb0.y, a2 + bb0.z, a3 + bb0.w);
            float4 o1 = make_float4(a4 + bb1.x, a5 + bb1.y, a6 + bb1.z, a7 + bb1.w);
            *(float4*)&g_pre[(size_t)node * 128 + cg * 8] = o0;
            *(float4*)&g_pre[(size_t)node * 128 + cg * 8 + 4] = o1;
        }
    }
}

// ---------------------------------------------------------------------------
// Aggregate: one warp per node, chunk-of-4 software pipeline, f32x2 micro-GEMM.
//   M[v] = mean_e relu(pre[src_e] + ea[e] @ W1[128:144,:])
// ---------------------------------------------------------------------------
struct Chunk {
    float4 pr[4];
    float  eav[4];
    int    m;
};

__device__ __forceinline__ void load_chunk(Chunk& c, int i, int end, int lane,
                                           const float4* __restrict__ pre4,
                                           const float* __restrict__ ea) {
    c.m = end - i;
    if (c.m > 4) c.m = 4;
    int2 p = make_int2(0, 0);
    if (lane < c.m) p = g_pairs[i + lane];
#pragma unroll
    for (int j = 0; j < 4; j++) {
        const int ej = __shfl_sync(0xffffffffu, p.x, j);
        const int sj = __shfl_sync(0xffffffffu, p.y, j);
        if (j < c.m) {
            c.pr[j]  = pre4[(size_t)sj * 32 + lane];
            c.eav[j] = (lane < 16) ? ea[(size_t)ej * 16 + lane] : 0.f;
        }
    }
}

__device__ __forceinline__ void compute_chunk(const Chunk& c, float4& acc,
                                              const float4 (*W1b)[32], int lane) {
#pragma unroll
    for (int j = 0; j < 4; j++) {
        if (j >= c.m) break;
        unsigned long long t0 = 0ull, t1 = 0ull;
#pragma unroll
        for (int k = 0; k < 16; k++) {
            const float a = __shfl_sync(0xffffffffu, c.eav[j], k);
            unsigned long long ap; PACK_F32X2(ap, a, a);
            const ulonglong2 wp = *(const ulonglong2*)&W1b[k][lane];
            FMA_F32X2(t0, ap, wp.x, t0);
            FMA_F32X2(t1, ap, wp.y, t1);
        }
        float tx, ty, tz, tw;
        UNPACK_F32X2(tx, ty, t0);
        UNPACK_F32X2(tz, tw, t1);
        acc.x += fmaxf(c.pr[j].x + tx, 0.f);
        acc.y += fmaxf(c.pr[j].y + ty, 0.f);
        acc.z += fmaxf(c.pr[j].z + tz, 0.f);
        acc.w += fmaxf(c.pr[j].w + tw, 0.f);
    }
}

__global__ __launch_bounds__(256) void agg_kernel(const float* __restrict__ ea,
                                                  const float* __restrict__ W1,
                                                  int nN) {
    __shared__ __align__(16) float4 W1b[16][32];
    const int tid = threadIdx.x;
    for (int idx = tid; idx < 512; idx += 256) {
        const int k = idx >> 5, c = idx & 31;
        W1b[k][c] = *(const float4*)&W1[(size_t)(128 + k) * 128 + c * 4];
    }
    __syncthreads();

    const int lane = tid & 31;
    const int v = blockIdx.x * 8 + (tid >> 5);
    if (v >= nN) return;

    const int beg = g_off[v];
    const int cnt = g_cnt[v];
    const int end = beg + cnt;
    const float4* pre4 = (const float4*)g_pre;

    float4 acc = make_float4(0.f, 0.f, 0.f, 0.f);

    Chunk c0, c1;
    int i = beg;
    if (i < end) {
        load_chunk(c0, i, end, lane, pre4, ea);
        i += 4;
        while (i < end) {
            load_chunk(c1, i, end, lane, pre4, ea);   // prefetch next
            i += 4;
            compute_chunk(c0, acc, W1b, lane);        // compute current
            c0 = c1;
        }
        compute_chunk(c0, acc, W1b, lane);
    }

    const float inv = (cnt > 0) ? (1.f / (float)cnt) : 0.f;
    acc.x *= inv; acc.y *= inv; acc.z *= inv; acc.w *= inv;
    ((float4*)g_M)[(size_t)v * 32 + lane] = acc;
}

// ---------------------------------------------------------------------------
// Node kernel: fused 3-GEMM chain, in-place A buffer, f32x2 inner loop.
//   h1 = cnt>0 ? M @ W2 + b2 : 0
//   h2 = relu(h1 @ W3 + b3)
//   out = h2 @ W4 + b4
// ---------------------------------------------------------------------------
__device__ __forceinline__ void gemm128(const float* __restrict__ Ain,
                                        const float* __restrict__ Wg,
                                        float* __restrict__ Wc,
                                        float acc[4][8], int rg, int cg, int tid) {
    unsigned long long acc2[4][4];
#pragma unroll
    for (int i = 0; i < 4; i++)
#pragma unroll
        for (int j = 0; j < 4; j++) acc2[i][j] = 0ull;

    for (int k0 = 0; k0 < 128; k0 += 32) {
        const int k = tid >> 5;
        const int c = (tid & 31) * 4;
#pragma unroll
        for (int kk = 0; kk < 32; kk += 8)
            *(float4*)&Wc[(k + kk) * 128 + c] =
                *(const float4*)&Wg[(size_t)(k0 + k + kk) * 128 + c];
        __syncthreads();
#pragma unroll
        for (int k2 = 0; k2 < 32; k2++) {
            const ulonglong2 wa = *(const ulonglong2*)&Wc[k2 * 128 + cg * 8];
            const ulonglong2 wb = *(const ulonglong2*)&Wc[k2 * 128 + cg * 8 + 4];
#pragma unroll
            for (int i = 0; i < 4; i++) {
                const float a = Ain[(rg * 4 + i) * 129 + k0 + k2];
                unsigned long long ap; PACK_F32X2(ap, a, a);
                FMA_F32X2(acc2[i][0], ap, wa.x, acc2[i][0]);
                FMA_F32X2(acc2[i][1], ap, wa.y, acc2[i][1]);
                FMA_F32X2(acc2[i][2], ap, wb.x, acc2[i][2]);
                FMA_F32X2(acc2[i][3], ap, wb.y, acc2[i][3]);
            }
        }
        __syncthreads();   // all reads of Ain complete after this
    }

#pragma unroll
    for (int i = 0; i < 4; i++) {
        UNPACK_F32X2(acc[i][0], acc[i][1], acc2[i][0]);
        UNPACK_F32X2(acc[i][2], acc[i][3], acc2[i][1]);
        UNPACK_F32X2(acc[i][4], acc[i][5], acc2[i][2]);
        UNPACK_F32X2(acc[i][6], acc[i][7], acc2[i][3]);
    }
}

__global__ __launch_bounds__(256, 3) void node_kernel(const float* __restrict__ W2,
                                                      const float* __restrict__ b2,
                                                      const float* __restrict__ W3,
                                                      const float* __restrict__ b3,
                                                      const float* __restrict__ W4,
                                                      const float* __restrict__ b4,
                                                      float* __restrict__ out, int n) {
    extern __shared__ float sm[];
    float* A  = sm;                      // [64][129]
    float* Wc = sm + 64 * 129;           // [32][128]; 8256 floats = 33024 B, 16B-aligned
    float* zf = Wc + 32 * 128;           // [64] cnt==0 flags

    const int tid = threadIdx.x;
    const int n0 = blockIdx.x * 64;
    const int rg = tid & 15;
    const int cg = tid >> 4;

    // Load mean operand (already divided) into A, flag empty nodes.
    {
        const int r = tid >> 2;
        const int q = (tid & 3) * 4;
        const int node = n0 + r;
        if ((tid & 3) == 0)
            zf[r] = (node < n && g_cnt[node] > 0) ? 0.f : 1.f;
#pragma unroll
        for (int k = q; k < 128; k += 16) {
            float4 v = make_float4(0.f, 0.f, 0.f, 0.f);
            if (node < n) v = *(const float4*)&g_M[(size_t)node * 128 + k];
            A[r * 129 + k]     = v.x;
            A[r * 129 + k + 1] = v.y;
            A[r * 129 + k + 2] = v.z;
            A[r * 129 + k + 3] = v.w;
        }
    }
    __syncthreads();

    float acc[4][8];

    // Stage 1: A = (cnt>0) ? A@W2 + b2 : 0   (in place — reads done pre-sync)
    gemm128(A, W2, Wc, acc, rg, cg, tid);
    {
        const float4 bb0 = *(const float4*)&b2[cg * 8];
        const float4 bb1 = *(const float4*)&b2[cg * 8 + 4];
        const float bb[8] = {bb0.x, bb0.y, bb0.z, bb0.w, bb1.x, bb1.y, bb1.z, bb1.w};
#pragma unroll
        for (int i = 0; i < 4; i++) {
            const int row = rg * 4 + i;
            const float zero = zf[row];
#pragma unroll
            for (int j = 0; j < 8; j++)
                A[row * 129 + cg * 8 + j] = (zero > 0.f) ? 0.f : (acc[i][j] + bb[j]);
        }
    }
    __syncthreads();

    // Stage 2: A = relu(A@W3 + b3)
    gemm128(A, W3, Wc, acc, rg, cg, tid);
    {
        const float4 bb0 = *(const float4*)&b3[cg * 8];
        const float4 bb1 = *(const float4*)&b3[cg * 8 + 4];
        const float bb[8] = {bb0.x, bb0.y, bb0.z, bb0.w, bb1.x, bb1.y, bb1.z, bb1.w};
#pragma unroll
        for (int i = 0; i < 4; i++) {
            const int row = rg * 4 + i;
#pragma unroll
            for (int j = 0; j < 8; j++)
                A[row * 129 + cg * 8 + j] = fmaxf(acc[i][j] + bb[j], 0.f);
        }
    }
    __syncthreads();

    // Stage 3: out = A@W4 + b4
    gemm128(A, W4, Wc, acc, rg, cg, tid);
    {
        const float4 bb0 = *(const float4*)&b4[cg * 8];
        const float4 bb1 = *(const float4*)&b4[cg * 8 + 4];
#pragma unroll
        for (int i = 0; i < 4; i++) {
            const int node = n0 + rg * 4 + i;
            if (node < n) {
                float4 o0 = make_float4(acc[i][0] + bb0.x, acc[i][1] + bb0.y,
                                        acc[i][2] + bb0.z, acc[i][3] + bb0.w);
                float4 o1 = make_float4(acc[i][4] + bb1.x, acc[i][5] + bb1.y,
                                        acc[i][6] + bb1.z, acc[i][7] + bb1.w);
                *(float4*)&out[(size_t)node * 128 + cg * 8] = o0;
                *(float4*)&out[(size_t)node * 128 + cg * 8 + 4] = o1;
            }
        }
    }
}

// ---------------------------------------------------------------------------
extern "C" void kernel_launch(void* const* d_in, const int* in_sizes, int n_in,
                              void* d_out, int out_size) {
    const float* x  = (const float*)d_in[0];
    const void*  ei = d_in[1];          // int32 or int64 — detected on device
    const float* ea = (const float*)d_in[2];
    // d_in[3] = batch (unused)
    const float* W1 = (const float*)d_in[4];
    const float* b1 = (const float*)d_in[5];
    const float* W2 = (const float*)d_in[6];
    const float* b2 = (const float*)d_in[7];
    const float* W3 = (const float*)d_in[8];
    const float* b3 = (const float*)d_in[9];
    const float* W4 = (const float*)d_in[10];
    const float* b4 = (const float*)d_in[11];
    float* out = (float*)d_out;

    const int n  = in_sizes[0] / 128;   // nodes
    const int nE = in_sizes[1] / 2;     // edges

    // One-time side stream + events for capture-legal fork/join.
    static cudaStream_t s2 = nullptr;
    static cudaEvent_t evFork = nullptr, evJoin = nullptr;
    if (s2 == nullptr) {
        cudaStreamCreateWithFlags(&s2, cudaStreamNonBlocking);
        cudaEventCreateWithFlags(&evFork, cudaEventDisableTiming);
        cudaEventCreateWithFlags(&evJoin, cudaEventDisableTiming);
    }

    void* pC = nullptr; void* pX = nullptr;
    cudaGetSymbolAddress(&pC, g_cnt);
    cudaGetSymbolAddress(&pX, g_cursor);

    // Fork: pre_kernel (independent of the sort phase) runs on s2.
    cudaEventRecord(evFork, 0);
    cudaStreamWaitEvent(s2, evFork, 0);
    const int nb64 = (n + 63) / 64;
    pre_kernel<<<nb64, 256, 0, s2>>>(x, W1, b1, n);
    cudaEventRecord(evJoin, s2);

    // Sort phase on the main stream.
    cudaMemsetAsync(pC, 0, (size_t)n * sizeof(int), 0);
    cudaMemsetAsync(pX, 0, sizeof(int), 0);

    const int ebl = (nE + 255) / 256;
    const int nbl = (n + 255) / 256;
    detect_kernel<<<1, 256>>>((const int*)ei, 2 * nE);
    hist_kernel<<<ebl, 256>>>(ei, nE, n);
    offset_kernel<<<nbl, 256>>>(n);
    scatter_kernel<<<ebl, 256>>>(ei, nE, n);

    // Join: agg needs both the sorted pairs and g_pre.
    cudaStreamWaitEvent(0, evJoin, 0);
    agg_kernel<<<(n + 7) / 8, 256>>>(ea, W1, n);

    const size_t shmem = (size_t)(64 * 129 + 32 * 128 + 64) * sizeof(float);
    cudaFuncSetAttribute(node_kernel,
                         cudaFuncAttributeMaxDynamicSharedMemorySize, (int)shmem);
    node_kernel<<<nb64, 256, shmem>>>(W2, b2, W3, b3, W4, b4, out, n);
}